// round 15
// baseline (speedup 1.0000x reference)
#include <cuda_runtime.h>
#include <cuda_bf16.h>
#include <cuda_fp16.h>
#include <math.h>
#include <stdint.h>

// Problem constants
#define B_  2
#define S_  2048
#define HID_ 4096
#define NH_ 32
#define NKV_ 8
#define HD_ 128
#define M_TOT (B_ * S_)          // 4096
#define NKVD (NKV_ * HD_)        // 1024
#define NQKV (HID_ + 2 * NKVD)   // 6144 fused QKV output cols

// fp16 scratch
__device__ __half g_A2 [(size_t)M_TOT * HID_];
__device__ __half g_W3 [(size_t)NQKV  * HID_];
__device__ __half g_Wo2[(size_t)HID_  * HID_];
__device__ __half g_O2 [(size_t)M_TOT * HID_];
__device__ __half g_qh [(size_t)M_TOT * NH_  * HD_];
__device__ __half g_kh [(size_t)M_TOT * NKVD];
__device__ __half g_vf [(size_t)M_TOT * NKVD];
__device__ __half g_vth[(size_t)M_TOT * NKVD];   // [b][kvh][d][s]

// ---------------------------------------------------------------------------
struct alignas(8) HF4 { __half v[4]; };

// cvtH: fp32 -> fp16 flat (4 elems/thread; R13-proven form)
__global__ void cvtH_kernel(const float* __restrict__ src,
                            __half* __restrict__ dst, int total4) {
    int i = blockIdx.x * blockDim.x + threadIdx.x;
    if (i >= total4) return;
    float4 x = *(const float4*)(src + (size_t)i * 4);
    HF4 H;
    H.v[0] = __float2half_rn(x.x);
    H.v[1] = __float2half_rn(x.y);
    H.v[2] = __float2half_rn(x.z);
    H.v[3] = __float2half_rn(x.w);
    *(HF4*)(dst + (size_t)i * 4) = H;
}

// rope16: in-place RoPE on fp16 q/k (q prescaled by qsc)
#define ROPE_TOTAL (B_ * S_ * (NH_ + NKV_) * 64)

__global__ void rope16_kernel(__half* __restrict__ qh,
                              __half* __restrict__ kh,
                              const int* __restrict__ pos_ids, float qsc) {
    int idx = blockIdx.x * blockDim.x + threadIdx.x;
    if (idx >= ROPE_TOTAL) return;
    int d    = idx & 63;
    int rest = idx >> 6;
    int head = rest % (NH_ + NKV_);
    rest    /= (NH_ + NKV_);
    int s = rest % S_;
    int b = rest / S_;

    float inv = powf(10000.0f, -(float)d * (1.0f / 64.0f));
    float ang = (float)pos_ids[s] * inv;
    float c = cosf(ang), sn = sinf(ang);

    __half* base = (head < NH_)
        ? qh + ((size_t)(b * S_ + s) * NH_ + head) * HD_
        : kh + ((size_t)(b * S_ + s) * NKV_ + (head - NH_)) * HD_;
    float sc = (head < NH_) ? qsc : 1.0f;

    float x1 = __half2float(base[d]), x2 = __half2float(base[d + 64]);
    base[d]      = __float2half_rn((x1 * c - x2 * sn) * sc);
    base[d + 64] = __float2half_rn((x2 * c + x1 * sn) * sc);
}

// vt16: fp16 v [b*S+s][kvh][d] -> fp16 [b][kvh][d][s]
__global__ void vt16_kernel(const __half* __restrict__ v,
                            __half* __restrict__ th) {
    int i = blockIdx.x * blockDim.x + threadIdx.x;
    int s    = i % S_;
    int rest = i / S_;
    int d4   = rest % (HD_ / 4);
    rest    /= (HD_ / 4);
    int kvh  = rest % NKV_;
    int b    = rest / NKV_;
    HF4 x = *(const HF4*)(v + ((size_t)(b * S_ + s) * NKV_ + kvh) * HD_ + d4 * 4);
#pragma unroll
    for (int j = 0; j < 4; j++) {
        size_t o = ((size_t)(b * NKV_ + kvh) * HD_ + d4 * 4 + j) * S_ + s;
        th[o] = x.v[j];
    }
}

// ---------------------------------------------------------------------------
// mma / ldmatrix helpers
// ---------------------------------------------------------------------------
__device__ __forceinline__ void ldsm4(uint32_t* r, uint32_t addr) {
    asm volatile("ldmatrix.sync.aligned.m8n8.x4.shared.b16 {%0,%1,%2,%3}, [%4];\n"
                 : "=r"(r[0]), "=r"(r[1]), "=r"(r[2]), "=r"(r[3]) : "r"(addr));
}
__device__ __forceinline__ void mma_f16(float* c, const uint32_t* a,
                                        uint32_t b0, uint32_t b1) {
    asm volatile("mma.sync.aligned.m16n8k16.row.col.f32.f16.f16.f32 "
                 "{%0,%1,%2,%3}, {%4,%5,%6,%7}, {%8,%9}, {%0,%1,%2,%3};\n"
                 : "+f"(c[0]), "+f"(c[1]), "+f"(c[2]), "+f"(c[3])
                 : "r"(a[0]), "r"(a[1]), "r"(a[2]), "r"(a[3]), "r"(b0), "r"(b1));
}
__device__ __forceinline__ uint32_t cvt_f16x2(float lo, float hi) {
    uint32_t r;
    asm("cvt.rn.f16x2.f32 %0, %1, %2;" : "=r"(r) : "f"(hi), "f"(lo));
    return r;
}

// ---------------------------------------------------------------------------
// fp16 tensor-core GEMM (NT): 128x128 tile, BK=64, 3-stage cp.async,
// 256 threads, warp tile 64x32. ONE barrier per 64-K (64 mmas between syncs).
// 108KB dynamic smem -> 1 CTA/SM, 8 warps (2/SMSP, flash-like profile).
// Epilogue routes 128-col tiles to (C0,C1,C2); half_out selects output type.
// ---------------------------------------------------------------------------
#define HG_BK 64
#define HG_LDS 72
#define HG_MAT_ELEMS (128 * HG_LDS)                 // 9216 per matrix
#define HG_STAGE_ELEMS (2 * HG_MAT_ELEMS)           // A + B
#define HG_STAGE_BYTES (HG_STAGE_ELEMS * 2)         // 36864
#define HG_SMEM_BYTES (3 * HG_STAGE_BYTES)          // 110592

__global__ __launch_bounds__(256, 1) void hgemm_nt(
    const __half* __restrict__ A, const __half* __restrict__ B,
    void* __restrict__ C0, void* __restrict__ C1, void* __restrict__ C2,
    int M, int K, int half_out) {
    extern __shared__ __half hsm[];
    const uint32_t s0 = (uint32_t)__cvta_generic_to_shared(hsm);

    const int t    = threadIdx.x;
    const int lane = t & 31;
    const int w    = t >> 5;
    const int wm   = w >> 2;
    const int wn   = w & 3;

    const __half* Ab = A + (size_t)blockIdx.y * 128 * K;
    const __half* Bb = B + (size_t)blockIdx.x * 128 * K;

    const int ldr = t >> 1;           // 0..127 (row)
    const int ldc = (t & 1) * 32;     // 0 or 32

    auto load_tile = [&](int kt, int st) {
        const uint32_t stb = s0 + st * HG_STAGE_BYTES;
        const __half* ga = Ab + (size_t)ldr * K + kt * HG_BK + ldc;
        const __half* gb = Bb + (size_t)ldr * K + kt * HG_BK + ldc;
#pragma unroll
        for (int j = 0; j < 4; j++) {
            int col = ldc + j * 8;
            asm volatile("cp.async.cg.shared.global [%0], [%1], 16;\n"
                         :: "r"(stb + (ldr * HG_LDS + col) * 2), "l"(ga + j * 8));
            asm volatile("cp.async.cg.shared.global [%0], [%1], 16;\n"
                         :: "r"(stb + (HG_MAT_ELEMS + ldr * HG_LDS + col) * 2),
                            "l"(gb + j * 8));
        }
    };

    const int KT = K / HG_BK;
    load_tile(0, 0);
    asm volatile("cp.async.commit_group;\n");
    load_tile(1, 1);
    asm volatile("cp.async.commit_group;\n");

    float acc[4][4][4];
#pragma unroll
    for (int i = 0; i < 4; i++)
#pragma unroll
        for (int j = 0; j < 4; j++)
#pragma unroll
            for (int r = 0; r < 4; r++) acc[i][j][r] = 0.f;

    const int g  = lane >> 3;
    const int lr = lane & 7;
    const int a_row = ((g & 1) << 3) + lr;
    const int a_k   = (g >> 1) << 3;
    const int b_row = ((g >> 1) << 3) + lr;
    const int b_k   = (g & 1) << 3;

    for (int kt = 0; kt < KT; kt++) {
        asm volatile("cp.async.wait_group 1;\n");
        __syncthreads();
        // stage (kt+2)%3 was consumed at kt-1; all warps passed that barrier
        if (kt + 2 < KT) load_tile(kt + 2, (kt + 2) % 3);
        asm volatile("cp.async.commit_group;\n");

        const uint32_t stb = s0 + (kt % 3) * HG_STAGE_BYTES;
        const uint32_t asb = stb;
        const uint32_t bsb = stb + HG_MAT_ELEMS * 2;

#pragma unroll
        for (int ks = 0; ks < 4; ks++) {
            uint32_t af[4][4];
            uint32_t bf_[4][2];
#pragma unroll
            for (int mf = 0; mf < 4; mf++) {
                int row = wm * 64 + mf * 16 + a_row;
                ldsm4(af[mf], asb + (row * HG_LDS + ks * 16 + a_k) * 2);
            }
#pragma unroll
            for (int np = 0; np < 2; np++) {
                int row = wn * 32 + np * 16 + b_row;
                uint32_t tmp[4];
                ldsm4(tmp, bsb + (row * HG_LDS + ks * 16 + b_k) * 2);
                bf_[np*2][0] = tmp[0]; bf_[np*2][1] = tmp[1];
                bf_[np*2+1][0] = tmp[2]; bf_[np*2+1][1] = tmp[3];
            }
#pragma unroll
            for (int mf = 0; mf < 4; mf++)
#pragma unroll
                for (int nf = 0; nf < 4; nf++)
                    mma_f16(acc[mf][nf], af[mf], bf_[nf][0], bf_[nf][1]);
        }
    }

    // epilogue with QKV column routing
    const int gc0 = blockIdx.x * 128;
    void* Cd; int cstride, cbase;
    if (gc0 < HID_)                { Cd = C0; cstride = NH_ * HD_; cbase = 0; }
    else if (gc0 < HID_ + NKVD)    { Cd = C1; cstride = NKVD;      cbase = HID_; }
    else                           { Cd = C2; cstride = NKVD;      cbase = HID_ + NKVD; }

#pragma unroll
    for (int mf = 0; mf < 4; mf++) {
        int row = blockIdx.y * 128 + wm * 64 + mf * 16 + (lane >> 2);
#pragma unroll
        for (int nf = 0; nf < 4; nf++) {
            int col = gc0 + wn * 32 + nf * 8 + (lane & 3) * 2 - cbase;
            if (half_out) {
                __half* Ch = (__half*)Cd;
                __half2 v0 = __floats2half2_rn(acc[mf][nf][0], acc[mf][nf][1]);
                __half2 v1 = __floats2half2_rn(acc[mf][nf][2], acc[mf][nf][3]);
                *(__half2*)&Ch[(size_t)row * cstride + col]       = v0;
                *(__half2*)&Ch[(size_t)(row + 8) * cstride + col] = v1;
            } else {
                float* Cf = (float*)Cd;
                float2 v0 = {acc[mf][nf][0], acc[mf][nf][1]};
                float2 v1 = {acc[mf][nf][2], acc[mf][nf][3]};
                *(float2*)&Cf[(size_t)row * cstride + col]       = v0;
                *(float2*)&Cf[(size_t)(row + 8) * cstride + col] = v1;
            }
        }
    }
}

// ---------------------------------------------------------------------------
// Tensor-core flash attention, single-term fp16, fp16 output (verified R14).
// ---------------------------------------------------------------------------
#define FQ_LDS 136
#define FV_LDS 72
#define F_Q 0
#define F_STAGE0 17408
#define F_STAGE (8704 + 9216)
#define F_K 0
#define F_VT 8704
#define FLASH_SMEM_ELEMS (F_STAGE0 + 2 * F_STAGE)
#define FLASH_SMEM_BYTES (FLASH_SMEM_ELEMS * 2)

__global__ __launch_bounds__(256, 1) void flash_tc(
    const __half* __restrict__ qh, const __half* __restrict__ kh,
    const __half* __restrict__ vth, __half* __restrict__ o) {
    const int qt  = gridDim.x - 1 - blockIdx.x;
    const int h   = blockIdx.y;
    const int b   = blockIdx.z;
    const int kvh = h >> 2;

    extern __shared__ __half fsm[];
    const uint32_t sb = (uint32_t)__cvta_generic_to_shared(fsm);

    const int t    = threadIdx.x;
    const int lane = t & 31;
    const int w    = t >> 5;

    {
        int r = t >> 1;
        const __half* gq = qh + ((size_t)(b * S_ + qt * 128 + r) * NH_ + h) * HD_;
#pragma unroll
        for (int j = 0; j < 8; j++) {
            int col = (t & 1) * 64 + j * 8;
            uint32_t sh = sb + (F_Q + r * FQ_LDS + col) * 2;
            asm volatile("cp.async.cg.shared.global [%0], [%1], 16;\n" :: "r"(sh), "l"(gq + col));
        }
        asm volatile("cp.async.commit_group;\n");
    }

    auto load_kv = [&](int kt, int st) {
        uint32_t stb = sb + (F_STAGE0 + st * F_STAGE) * 2;
        {
            int r  = t >> 2;
            int cb = (t & 3) * 32;
            size_t go = ((size_t)(b * S_ + kt * 64 + r) * NKV_ + kvh) * HD_;
#pragma unroll
            for (int j = 0; j < 4; j++) {
                int col = cb + j * 8;
                asm volatile("cp.async.cg.shared.global [%0], [%1], 16;\n"
                             :: "r"(stb + (F_K + r * FQ_LDS + col) * 2), "l"(kh + go + col));
            }
        }
        {
            int rv = t >> 1;
            int cv = (t & 1) * 32;
            size_t go = ((size_t)(b * NKV_ + kvh) * HD_ + rv) * S_ + kt * 64;
#pragma unroll
            for (int j = 0; j < 4; j++) {
                int col = cv + j * 8;
                asm volatile("cp.async.cg.shared.global [%0], [%1], 16;\n"
                             :: "r"(stb + (F_VT + rv * FV_LDS + col) * 2), "l"(vth + go + col));
            }
        }
    };

    const int ktmax = 2 * qt + 1;
    load_kv(0, 0);
    asm volatile("cp.async.commit_group;\n");
    if (ktmax >= 1) load_kv(1, 1);
    asm volatile("cp.async.commit_group;\n");

    const int g  = lane >> 3;
    const int lr = lane & 7;
    const int a_row = ((g & 1) << 3) + lr;
    const int a_k   = (g >> 1) << 3;
    const int b_row = ((g >> 1) << 3) + lr;
    const int b_k   = (g & 1) << 3;

    float out[16][4];
#pragma unroll
    for (int i = 0; i < 16; i++)
#pragma unroll
        for (int j = 0; j < 4; j++) out[i][j] = 0.f;
    float m0 = -INFINITY, m1 = -INFINITY, l0 = 0.f, l1 = 0.f;

    const int qrow_base = qt * 128 + w * 16;

    for (int kt = 0; kt <= ktmax; kt++) {
        asm volatile("cp.async.wait_group 1;\n");
        __syncthreads();
        const int st = kt & 1;
        const uint32_t stb = sb + (F_STAGE0 + st * F_STAGE) * 2;

        if (kt * 64 <= qrow_base + 15) {
            float accs[8][4];
#pragma unroll
            for (int i = 0; i < 8; i++)
#pragma unroll
                for (int j = 0; j < 4; j++) accs[i][j] = 0.f;

#pragma unroll
            for (int kc = 0; kc < 8; kc++) {
                uint32_t aH[4];
                ldsm4(aH, sb + (F_Q + (w * 16 + a_row) * FQ_LDS + kc * 16 + a_k) * 2);
#pragma unroll
                for (int nf2 = 0; nf2 < 4; nf2++) {
                    uint32_t bh[4];
                    ldsm4(bh, stb + (F_K + (nf2 * 16 + b_row) * FQ_LDS + kc * 16 + b_k) * 2);
                    mma_f16(accs[nf2 * 2],     aH, bh[0], bh[1]);
                    mma_f16(accs[nf2 * 2 + 1], aH, bh[2], bh[3]);
                }
            }

            if (kt * 64 + 63 > qrow_base) {
                int r0 = qrow_base + (lane >> 2);
#pragma unroll
                for (int nf = 0; nf < 8; nf++) {
#pragma unroll
                    for (int e = 0; e < 4; e++) {
                        int col = kt * 64 + nf * 8 + (lane & 3) * 2 + (e & 1);
                        int row = r0 + (e >> 1) * 8;
                        if (col > row) accs[nf][e] = -1.0e30f;
                    }
                }
            }

            float mx0 = -INFINITY, mx1 = -INFINITY;
#pragma unroll
            for (int nf = 0; nf < 8; nf++) {
                mx0 = fmaxf(mx0, fmaxf(accs[nf][0], accs[nf][1]));
                mx1 = fmaxf(mx1, fmaxf(accs[nf][2], accs[nf][3]));
            }
            mx0 = fmaxf(mx0, __shfl_xor_sync(0xffffffffu, mx0, 1));
            mx0 = fmaxf(mx0, __shfl_xor_sync(0xffffffffu, mx0, 2));
            mx1 = fmaxf(mx1, __shfl_xor_sync(0xffffffffu, mx1, 1));
            mx1 = fmaxf(mx1, __shfl_xor_sync(0xffffffffu, mx1, 2));
            float mn0 = fmaxf(m0, mx0), mn1 = fmaxf(m1, mx1);
            float c0 = exp2f(m0 - mn0), c1 = exp2f(m1 - mn1);
            m0 = mn0; m1 = mn1;

            float s0 = 0.f, s1 = 0.f;
#pragma unroll
            for (int nf = 0; nf < 8; nf++) {
                accs[nf][0] = exp2f(accs[nf][0] - mn0);
                accs[nf][1] = exp2f(accs[nf][1] - mn0);
                accs[nf][2] = exp2f(accs[nf][2] - mn1);
                accs[nf][3] = exp2f(accs[nf][3] - mn1);
                s0 += accs[nf][0] + accs[nf][1];
                s1 += accs[nf][2] + accs[nf][3];
            }
            s0 += __shfl_xor_sync(0xffffffffu, s0, 1);
            s0 += __shfl_xor_sync(0xffffffffu, s0, 2);
            s1 += __shfl_xor_sync(0xffffffffu, s1, 1);
            s1 += __shfl_xor_sync(0xffffffffu, s1, 2);
            l0 = l0 * c0 + s0;
            l1 = l1 * c1 + s1;

            uint32_t pH[4][4];
#pragma unroll
            for (int kc2 = 0; kc2 < 4; kc2++) {
#pragma unroll
                for (int q4 = 0; q4 < 4; q4++) {
                    int nf = kc2 * 2 + (q4 >> 1);
                    int e0 = (q4 & 1) * 2;
                    pH[kc2][q4] = cvt_f16x2(accs[nf][e0], accs[nf][e0 + 1]);
                }
            }

#pragma unroll
            for (int i = 0; i < 16; i++) {
                out[i][0] *= c0; out[i][1] *= c0;
                out[i][2] *= c1; out[i][3] *= c1;
            }

#pragma unroll
            for (int kc2 = 0; kc2 < 4; kc2++) {
#pragma unroll
                for (int nd = 0; nd < 8; nd++) {
                    uint32_t bh[4];
                    ldsm4(bh, stb + (F_VT + (nd * 16 + b_row) * FV_LDS + kc2 * 16 + b_k) * 2);
                    mma_f16(out[nd * 2],     pH[kc2], bh[0], bh[1]);
                    mma_f16(out[nd * 2 + 1], pH[kc2], bh[2], bh[3]);
                }
            }
        }

        __syncthreads();
        if (kt + 2 <= ktmax) load_kv(kt + 2, st);
        asm volatile("cp.async.commit_group;\n");
    }

    float inv0 = 1.0f / l0, inv1 = 1.0f / l1;
    int r0 = qt * 128 + w * 16 + (lane >> 2);
#pragma unroll
    for (int nfd = 0; nfd < 16; nfd++) {
        int col = nfd * 8 + (lane & 3) * 2;
        __half2 v0 = __floats2half2_rn(out[nfd][0] * inv0, out[nfd][1] * inv0);
        __half2 v1 = __floats2half2_rn(out[nfd][2] * inv1, out[nfd][3] * inv1);
        *(__half2*)&o[((size_t)(b * S_ + r0) * NH_ + h) * HD_ + col]       = v0;
        *(__half2*)&o[((size_t)(b * S_ + r0 + 8) * NH_ + h) * HD_ + col]   = v1;
    }
}

// ---------------------------------------------------------------------------
// Launch
// ---------------------------------------------------------------------------
extern "C" void kernel_launch(void* const* d_in, const int* in_sizes, int n_in,
                              void* d_out, int out_size) {
    const float* hidden = (const float*)d_in[0];
    const int*   pos    = (const int*)  d_in[2];
    const float* wq     = (const float*)d_in[3];
    const float* wk     = (const float*)d_in[4];
    const float* wv     = (const float*)d_in[5];
    const float* wo     = (const float*)d_in[6];
    float* out = (float*)d_out;

    __half *a2, *w3, *wo2, *o2, *qhp, *khp, *vfp, *vthp;
    cudaGetSymbolAddress((void**)&a2, g_A2);
    cudaGetSymbolAddress((void**)&w3, g_W3);
    cudaGetSymbolAddress((void**)&wo2, g_Wo2);
    cudaGetSymbolAddress((void**)&o2, g_O2);
    cudaGetSymbolAddress((void**)&qhp, g_qh);
    cudaGetSymbolAddress((void**)&khp, g_kh);
    cudaGetSymbolAddress((void**)&vfp, g_vf);
    cudaGetSymbolAddress((void**)&vthp, g_vth);

    const int big4   = (M_TOT * HID_) / 4;
    const int small4 = (NKVD * HID_) / 4;
    cvtH_kernel<<<(big4 + 255) / 256, 256>>>(hidden, a2, big4);
    cvtH_kernel<<<(big4 + 255) / 256, 256>>>(wq, w3, big4);
    cvtH_kernel<<<(small4 + 255) / 256, 256>>>(wk, w3 + (size_t)HID_ * HID_, small4);
    cvtH_kernel<<<(small4 + 255) / 256, 256>>>(wv, w3 + (size_t)(HID_ + NKVD) * HID_, small4);
    cvtH_kernel<<<(big4 + 255) / 256, 256>>>(wo, wo2, big4);

    cudaFuncSetAttribute(hgemm_nt, cudaFuncAttributeMaxDynamicSharedMemorySize,
                         HG_SMEM_BYTES);

    // fused QKV projection -> fp16 outputs
    hgemm_nt<<<dim3(NQKV / 128, M_TOT / 128), 256, HG_SMEM_BYTES>>>(
        a2, w3, qhp, khp, vfp, M_TOT, HID_, 1);

    // in-place fp16 RoPE (q prescaled by 1/sqrt(HD)*log2(e))
    const float QSC = 0.08838834764831845f * 1.4426950408889634f;
    rope16_kernel<<<(ROPE_TOTAL + 255) / 256, 256>>>(qhp, khp, pos, QSC);
    vt16_kernel<<<(B_ * NKV_ * (HD_ / 4) * S_ + 255) / 256, 256>>>(vfp, vthp);

    cudaFuncSetAttribute(flash_tc, cudaFuncAttributeMaxDynamicSharedMemorySize,
                         FLASH_SMEM_BYTES);
    flash_tc<<<dim3(S_ / 128, NH_, B_), 256, FLASH_SMEM_BYTES>>>(qhp, khp, vthp, o2);

    // output projection -> fp32 out
    hgemm_nt<<<dim3(HID_ / 128, M_TOT / 128), 256, HG_SMEM_BYTES>>>(
        o2, wo2, out, out, out, M_TOT, HID_, 0);
}

// round 16
// speedup vs baseline: 1.3170x; 1.3170x over previous
#include <cuda_runtime.h>
#include <cuda_bf16.h>
#include <cuda_fp16.h>
#include <math.h>
#include <stdint.h>

// Problem constants
#define B_  2
#define S_  2048
#define HID_ 4096
#define NH_ 32
#define NKV_ 8
#define HD_ 128
#define M_TOT (B_ * S_)          // 4096
#define NKVD (NKV_ * HD_)        // 1024
#define NQKV (HID_ + 2 * NKVD)   // 6144 fused QKV output cols

// fp32 scratch (QKV projection outputs)
__device__ float g_q[(size_t)M_TOT * NH_ * HD_];
__device__ float g_k[(size_t)M_TOT * NKVD];
__device__ float g_v[(size_t)M_TOT * NKVD];

// fp16 scratch
__device__ __half g_A2 [(size_t)M_TOT * HID_];
__device__ __half g_W3 [(size_t)NQKV  * HID_];
__device__ __half g_Wo2[(size_t)HID_  * HID_];
__device__ __half g_O2 [(size_t)M_TOT * HID_];   // flash writes fp16 directly
__device__ __half g_qh [(size_t)M_TOT * NH_  * HD_];
__device__ __half g_kh [(size_t)M_TOT * NKVD];
__device__ __half g_vth[(size_t)M_TOT * NKVD];   // [b][kvh][d][s]

// ---------------------------------------------------------------------------
struct alignas(8) HF4 { __half v[4]; };

// cvtH: fp32 -> fp16 flat (R13-proven form)
__global__ void cvtH_kernel(const float* __restrict__ src,
                            __half* __restrict__ dst, int total4) {
    int i = blockIdx.x * blockDim.x + threadIdx.x;
    if (i >= total4) return;
    float4 x = *(const float4*)(src + (size_t)i * 4);
    HF4 H;
    H.v[0] = __float2half_rn(x.x);
    H.v[1] = __float2half_rn(x.y);
    H.v[2] = __float2half_rn(x.z);
    H.v[3] = __float2half_rn(x.w);
    *(HF4*)(dst + (size_t)i * 4) = H;
}

// ropecvt: apply RoPE to fp32 q/k and write fp16 (q prescaled by qsc)
#define ROPE_TOTAL (B_ * S_ * (NH_ + NKV_) * 64)

__global__ void ropecvt_kernel(const float* __restrict__ q,
                               const float* __restrict__ k,
                               const int* __restrict__ pos_ids,
                               __half* __restrict__ qh,
                               __half* __restrict__ kh, float qsc) {
    int idx = blockIdx.x * blockDim.x + threadIdx.x;
    if (idx >= ROPE_TOTAL) return;
    int d    = idx & 63;
    int rest = idx >> 6;
    int head = rest % (NH_ + NKV_);
    rest    /= (NH_ + NKV_);
    int s = rest % S_;
    int b = rest / S_;

    float inv = powf(10000.0f, -(float)d * (1.0f / 64.0f));
    float ang = (float)pos_ids[s] * inv;
    float c = cosf(ang), sn = sinf(ang);

    if (head < NH_) {
        size_t o = ((size_t)(b * S_ + s) * NH_ + head) * HD_;
        float x1 = q[o + d], x2 = q[o + d + 64];
        qh[o + d]      = __float2half_rn((x1 * c - x2 * sn) * qsc);
        qh[o + d + 64] = __float2half_rn((x2 * c + x1 * sn) * qsc);
    } else {
        size_t o = ((size_t)(b * S_ + s) * NKV_ + (head - NH_)) * HD_;
        float x1 = k[o + d], x2 = k[o + d + 64];
        kh[o + d]      = __float2half_rn(x1 * c - x2 * sn);
        kh[o + d + 64] = __float2half_rn(x2 * c + x1 * sn);
    }
}

// V transpose+cvt: g_v fp32 [b*S+s][kvh][d] -> fp16 [b][kvh][d][s]
__global__ void vt_kernel(const float* __restrict__ v,
                          __half* __restrict__ th) {
    int i = blockIdx.x * blockDim.x + threadIdx.x;
    int s    = i % S_;
    int rest = i / S_;
    int d4   = rest % (HD_ / 4);
    rest    /= (HD_ / 4);
    int kvh  = rest % NKV_;
    int b    = rest / NKV_;
    float4 x = *(const float4*)(v + ((size_t)(b * S_ + s) * NKV_ + kvh) * HD_ + d4 * 4);
    float xs[4] = {x.x, x.y, x.z, x.w};
#pragma unroll
    for (int j = 0; j < 4; j++) {
        size_t o = ((size_t)(b * NKV_ + kvh) * HD_ + d4 * 4 + j) * S_ + s;
        th[o] = __float2half_rn(xs[j]);
    }
}

// ---------------------------------------------------------------------------
// mma / ldmatrix helpers
// ---------------------------------------------------------------------------
__device__ __forceinline__ void ldsm4(uint32_t* r, uint32_t addr) {
    asm volatile("ldmatrix.sync.aligned.m8n8.x4.shared.b16 {%0,%1,%2,%3}, [%4];\n"
                 : "=r"(r[0]), "=r"(r[1]), "=r"(r[2]), "=r"(r[3]) : "r"(addr));
}
__device__ __forceinline__ void mma_f16(float* c, const uint32_t* a,
                                        uint32_t b0, uint32_t b1) {
    asm volatile("mma.sync.aligned.m16n8k16.row.col.f32.f16.f16.f32 "
                 "{%0,%1,%2,%3}, {%4,%5,%6,%7}, {%8,%9}, {%0,%1,%2,%3};\n"
                 : "+f"(c[0]), "+f"(c[1]), "+f"(c[2]), "+f"(c[3])
                 : "r"(a[0]), "r"(a[1]), "r"(a[2]), "r"(a[3]), "r"(b0), "r"(b1));
}
__device__ __forceinline__ uint32_t cvt_f16x2(float lo, float hi) {
    uint32_t r;
    asm("cvt.rn.f16x2.f32 %0, %1, %2;" : "=r"(r) : "f"(hi), "f"(lo));
    return r;
}

// ---------------------------------------------------------------------------
// fp16 tensor-core GEMM (NT): 128x128x32 tile, 256 threads, warp tile 64x32,
// 3-stage cp.async, 2 CTAs/SM (R13-proven). Epilogue routes QKV; fp32 output.
// ---------------------------------------------------------------------------
#define HG_BK 32
#define HG_LDS 40
#define HG_STAGE_ELEMS (128 * HG_LDS)
#define HG_STAGE_BYTES (HG_STAGE_ELEMS * 2)

__global__ __launch_bounds__(256, 2) void hgemm_nt(
    const __half* __restrict__ A, const __half* __restrict__ B,
    float* __restrict__ C0, float* __restrict__ C1, float* __restrict__ C2,
    int M, int K) {
    __shared__ __half As[3][HG_STAGE_ELEMS];
    __shared__ __half Bs[3][HG_STAGE_ELEMS];

    const int t    = threadIdx.x;
    const int lane = t & 31;
    const int w    = t >> 5;
    const int wm   = w >> 2;
    const int wn   = w & 3;

    const __half* Ab = A + (size_t)blockIdx.y * 128 * K;
    const __half* Bb = B + (size_t)blockIdx.x * 128 * K;

    const uint32_t as0 = (uint32_t)__cvta_generic_to_shared(&As[0][0]);
    const uint32_t bs0 = (uint32_t)__cvta_generic_to_shared(&Bs[0][0]);

    const int ldr = t >> 2;
    const int ldc = (t & 3) * 8;

    auto load_tile = [&](int kt, int st) {
#pragma unroll
        for (int it = 0; it < 2; it++) {
            int r = ldr + it * 64;
            const __half* ga = Ab + (size_t)r * K + kt * HG_BK + ldc;
            uint32_t sa = as0 + st * HG_STAGE_BYTES + (r * HG_LDS + ldc) * 2;
            asm volatile("cp.async.cg.shared.global [%0], [%1], 16;\n" :: "r"(sa), "l"(ga));
            const __half* gb = Bb + (size_t)r * K + kt * HG_BK + ldc;
            uint32_t sb = bs0 + st * HG_STAGE_BYTES + (r * HG_LDS + ldc) * 2;
            asm volatile("cp.async.cg.shared.global [%0], [%1], 16;\n" :: "r"(sb), "l"(gb));
        }
    };

    const int KT = K / HG_BK;
    load_tile(0, 0);
    asm volatile("cp.async.commit_group;\n");
    load_tile(1, 1);
    asm volatile("cp.async.commit_group;\n");

    float acc[4][4][4];
#pragma unroll
    for (int i = 0; i < 4; i++)
#pragma unroll
        for (int j = 0; j < 4; j++)
#pragma unroll
            for (int r = 0; r < 4; r++) acc[i][j][r] = 0.f;

    const int g  = lane >> 3;
    const int lr = lane & 7;
    const int a_row = ((g & 1) << 3) + lr;
    const int a_k   = (g >> 1) << 3;
    const int b_row = ((g >> 1) << 3) + lr;
    const int b_k   = (g & 1) << 3;

    for (int kt = 0; kt < KT; kt++) {
        asm volatile("cp.async.wait_group 1;\n");
        __syncthreads();
        if (kt + 2 < KT) load_tile(kt + 2, (kt + 2) % 3);
        asm volatile("cp.async.commit_group;\n");

        const int st = kt % 3;
        const uint32_t asb = as0 + st * HG_STAGE_BYTES;
        const uint32_t bsb = bs0 + st * HG_STAGE_BYTES;

#pragma unroll
        for (int ks = 0; ks < 2; ks++) {
            uint32_t af[4][4];
            uint32_t bf_[4][2];
#pragma unroll
            for (int mf = 0; mf < 4; mf++) {
                int row = wm * 64 + mf * 16 + a_row;
                ldsm4(af[mf], asb + (row * HG_LDS + ks * 16 + a_k) * 2);
            }
#pragma unroll
            for (int np = 0; np < 2; np++) {
                int row = wn * 32 + np * 16 + b_row;
                uint32_t tmp[4];
                ldsm4(tmp, bsb + (row * HG_LDS + ks * 16 + b_k) * 2);
                bf_[np*2][0] = tmp[0]; bf_[np*2][1] = tmp[1];
                bf_[np*2+1][0] = tmp[2]; bf_[np*2+1][1] = tmp[3];
            }
#pragma unroll
            for (int mf = 0; mf < 4; mf++)
#pragma unroll
                for (int nf = 0; nf < 4; nf++)
                    mma_f16(acc[mf][nf], af[mf], bf_[nf][0], bf_[nf][1]);
        }
    }

    const int gc0 = blockIdx.x * 128;
    float* Cd; int cstride, cbase;
    if (gc0 < HID_)                { Cd = C0; cstride = NH_ * HD_; cbase = 0; }
    else if (gc0 < HID_ + NKVD)    { Cd = C1; cstride = NKVD;      cbase = HID_; }
    else                           { Cd = C2; cstride = NKVD;      cbase = HID_ + NKVD; }

#pragma unroll
    for (int mf = 0; mf < 4; mf++) {
        int row = blockIdx.y * 128 + wm * 64 + mf * 16 + (lane >> 2);
#pragma unroll
        for (int nf = 0; nf < 4; nf++) {
            int col = gc0 + wn * 32 + nf * 8 + (lane & 3) * 2 - cbase;
            float2 v0 = {acc[mf][nf][0], acc[mf][nf][1]};
            float2 v1 = {acc[mf][nf][2], acc[mf][nf][3]};
            *(float2*)&Cd[(size_t)row * cstride + col]       = v0;
            *(float2*)&Cd[(size_t)(row + 8) * cstride + col] = v1;
        }
    }
}

// ---------------------------------------------------------------------------
// Tensor-core flash attention, single-term fp16, fp16 output.
// BQ=128, BK=64, HD=128, 256 threads (8 warps x 16 q-rows).
// ---------------------------------------------------------------------------
#define FQ_LDS 136
#define FV_LDS 72
#define F_Q 0
#define F_STAGE0 17408
#define F_STAGE (8704 + 9216)
#define F_K 0
#define F_VT 8704
#define FLASH_SMEM_ELEMS (F_STAGE0 + 2 * F_STAGE)
#define FLASH_SMEM_BYTES (FLASH_SMEM_ELEMS * 2)

__global__ __launch_bounds__(256, 1) void flash_tc(
    const __half* __restrict__ qh, const __half* __restrict__ kh,
    const __half* __restrict__ vth, __half* __restrict__ o) {
    const int qt  = gridDim.x - 1 - blockIdx.x;
    const int h   = blockIdx.y;
    const int b   = blockIdx.z;
    const int kvh = h >> 2;

    extern __shared__ __half fsm[];
    const uint32_t sb = (uint32_t)__cvta_generic_to_shared(fsm);

    const int t    = threadIdx.x;
    const int lane = t & 31;
    const int w    = t >> 5;

    {
        int r = t >> 1;
        const __half* gq = qh + ((size_t)(b * S_ + qt * 128 + r) * NH_ + h) * HD_;
#pragma unroll
        for (int j = 0; j < 8; j++) {
            int col = (t & 1) * 64 + j * 8;
            uint32_t sh = sb + (F_Q + r * FQ_LDS + col) * 2;
            asm volatile("cp.async.cg.shared.global [%0], [%1], 16;\n" :: "r"(sh), "l"(gq + col));
        }
        asm volatile("cp.async.commit_group;\n");
    }

    auto load_kv = [&](int kt, int st) {
        uint32_t stb = sb + (F_STAGE0 + st * F_STAGE) * 2;
        {
            int r  = t >> 2;
            int cb = (t & 3) * 32;
            size_t go = ((size_t)(b * S_ + kt * 64 + r) * NKV_ + kvh) * HD_;
#pragma unroll
            for (int j = 0; j < 4; j++) {
                int col = cb + j * 8;
                asm volatile("cp.async.cg.shared.global [%0], [%1], 16;\n"
                             :: "r"(stb + (F_K + r * FQ_LDS + col) * 2), "l"(kh + go + col));
            }
        }
        {
            int rv = t >> 1;
            int cv = (t & 1) * 32;
            size_t go = ((size_t)(b * NKV_ + kvh) * HD_ + rv) * S_ + kt * 64;
#pragma unroll
            for (int j = 0; j < 4; j++) {
                int col = cv + j * 8;
                asm volatile("cp.async.cg.shared.global [%0], [%1], 16;\n"
                             :: "r"(stb + (F_VT + rv * FV_LDS + col) * 2), "l"(vth + go + col));
            }
        }
    };

    const int ktmax = 2 * qt + 1;
    load_kv(0, 0);
    asm volatile("cp.async.commit_group;\n");
    if (ktmax >= 1) load_kv(1, 1);
    asm volatile("cp.async.commit_group;\n");

    const int g  = lane >> 3;
    const int lr = lane & 7;
    const int a_row = ((g & 1) << 3) + lr;
    const int a_k   = (g >> 1) << 3;
    const int b_row = ((g >> 1) << 3) + lr;
    const int b_k   = (g & 1) << 3;

    float out[16][4];
#pragma unroll
    for (int i = 0; i < 16; i++)
#pragma unroll
        for (int j = 0; j < 4; j++) out[i][j] = 0.f;
    float m0 = -INFINITY, m1 = -INFINITY, l0 = 0.f, l1 = 0.f;

    const int qrow_base = qt * 128 + w * 16;

    for (int kt = 0; kt <= ktmax; kt++) {
        asm volatile("cp.async.wait_group 1;\n");
        __syncthreads();
        const int st = kt & 1;
        const uint32_t stb = sb + (F_STAGE0 + st * F_STAGE) * 2;

        if (kt * 64 <= qrow_base + 15) {
            float accs[8][4];
#pragma unroll
            for (int i = 0; i < 8; i++)
#pragma unroll
                for (int j = 0; j < 4; j++) accs[i][j] = 0.f;

#pragma unroll
            for (int kc = 0; kc < 8; kc++) {
                uint32_t aH[4];
                ldsm4(aH, sb + (F_Q + (w * 16 + a_row) * FQ_LDS + kc * 16 + a_k) * 2);
#pragma unroll
                for (int nf2 = 0; nf2 < 4; nf2++) {
                    uint32_t bh[4];
                    ldsm4(bh, stb + (F_K + (nf2 * 16 + b_row) * FQ_LDS + kc * 16 + b_k) * 2);
                    mma_f16(accs[nf2 * 2],     aH, bh[0], bh[1]);
                    mma_f16(accs[nf2 * 2 + 1], aH, bh[2], bh[3]);
                }
            }

            if (kt * 64 + 63 > qrow_base) {
                int r0 = qrow_base + (lane >> 2);
#pragma unroll
                for (int nf = 0; nf < 8; nf++) {
#pragma unroll
                    for (int e = 0; e < 4; e++) {
                        int col = kt * 64 + nf * 8 + (lane & 3) * 2 + (e & 1);
                        int row = r0 + (e >> 1) * 8;
                        if (col > row) accs[nf][e] = -1.0e30f;
                    }
                }
            }

            float mx0 = -INFINITY, mx1 = -INFINITY;
#pragma unroll
            for (int nf = 0; nf < 8; nf++) {
                mx0 = fmaxf(mx0, fmaxf(accs[nf][0], accs[nf][1]));
                mx1 = fmaxf(mx1, fmaxf(accs[nf][2], accs[nf][3]));
            }
            mx0 = fmaxf(mx0, __shfl_xor_sync(0xffffffffu, mx0, 1));
            mx0 = fmaxf(mx0, __shfl_xor_sync(0xffffffffu, mx0, 2));
            mx1 = fmaxf(mx1, __shfl_xor_sync(0xffffffffu, mx1, 1));
            mx1 = fmaxf(mx1, __shfl_xor_sync(0xffffffffu, mx1, 2));
            float mn0 = fmaxf(m0, mx0), mn1 = fmaxf(m1, mx1);
            float c0 = exp2f(m0 - mn0), c1 = exp2f(m1 - mn1);
            m0 = mn0; m1 = mn1;

            float s0 = 0.f, s1 = 0.f;
#pragma unroll
            for (int nf = 0; nf < 8; nf++) {
                accs[nf][0] = exp2f(accs[nf][0] - mn0);
                accs[nf][1] = exp2f(accs[nf][1] - mn0);
                accs[nf][2] = exp2f(accs[nf][2] - mn1);
                accs[nf][3] = exp2f(accs[nf][3] - mn1);
                s0 += accs[nf][0] + accs[nf][1];
                s1 += accs[nf][2] + accs[nf][3];
            }
            s0 += __shfl_xor_sync(0xffffffffu, s0, 1);
            s0 += __shfl_xor_sync(0xffffffffu, s0, 2);
            s1 += __shfl_xor_sync(0xffffffffu, s1, 1);
            s1 += __shfl_xor_sync(0xffffffffu, s1, 2);
            l0 = l0 * c0 + s0;
            l1 = l1 * c1 + s1;

            uint32_t pH[4][4];
#pragma unroll
            for (int kc2 = 0; kc2 < 4; kc2++) {
#pragma unroll
                for (int q4 = 0; q4 < 4; q4++) {
                    int nf = kc2 * 2 + (q4 >> 1);
                    int e0 = (q4 & 1) * 2;
                    pH[kc2][q4] = cvt_f16x2(accs[nf][e0], accs[nf][e0 + 1]);
                }
            }

#pragma unroll
            for (int i = 0; i < 16; i++) {
                out[i][0] *= c0; out[i][1] *= c0;
                out[i][2] *= c1; out[i][3] *= c1;
            }

#pragma unroll
            for (int kc2 = 0; kc2 < 4; kc2++) {
#pragma unroll
                for (int nd = 0; nd < 8; nd++) {
                    uint32_t bh[4];
                    ldsm4(bh, stb + (F_VT + (nd * 16 + b_row) * FV_LDS + kc2 * 16 + b_k) * 2);
                    mma_f16(out[nd * 2],     pH[kc2], bh[0], bh[1]);
                    mma_f16(out[nd * 2 + 1], pH[kc2], bh[2], bh[3]);
                }
            }
        }

        __syncthreads();
        if (kt + 2 <= ktmax) load_kv(kt + 2, st);
        asm volatile("cp.async.commit_group;\n");
    }

    float inv0 = 1.0f / l0, inv1 = 1.0f / l1;
    int r0 = qt * 128 + w * 16 + (lane >> 2);
#pragma unroll
    for (int nfd = 0; nfd < 16; nfd++) {
        int col = nfd * 8 + (lane & 3) * 2;
        __half2 v0 = __floats2half2_rn(out[nfd][0] * inv0, out[nfd][1] * inv0);
        __half2 v1 = __floats2half2_rn(out[nfd][2] * inv1, out[nfd][3] * inv1);
        *(__half2*)&o[((size_t)(b * S_ + r0) * NH_ + h) * HD_ + col]       = v0;
        *(__half2*)&o[((size_t)(b * S_ + r0 + 8) * NH_ + h) * HD_ + col]   = v1;
    }
}

// ---------------------------------------------------------------------------
// Output-projection GEMM: fp16 in, fp32 out (plain, no routing)
// ---------------------------------------------------------------------------
__global__ __launch_bounds__(256, 2) void hgemm_out(
    const __half* __restrict__ A, const __half* __restrict__ B,
    float* __restrict__ C, int M, int K) {
    __shared__ __half As[3][HG_STAGE_ELEMS];
    __shared__ __half Bs[3][HG_STAGE_ELEMS];

    const int t    = threadIdx.x;
    const int lane = t & 31;
    const int w    = t >> 5;
    const int wm   = w >> 2;
    const int wn   = w & 3;

    const __half* Ab = A + (size_t)blockIdx.y * 128 * K;
    const __half* Bb = B + (size_t)blockIdx.x * 128 * K;

    const uint32_t as0 = (uint32_t)__cvta_generic_to_shared(&As[0][0]);
    const uint32_t bs0 = (uint32_t)__cvta_generic_to_shared(&Bs[0][0]);

    const int ldr = t >> 2;
    const int ldc = (t & 3) * 8;

    auto load_tile = [&](int kt, int st) {
#pragma unroll
        for (int it = 0; it < 2; it++) {
            int r = ldr + it * 64;
            const __half* ga = Ab + (size_t)r * K + kt * HG_BK + ldc;
            uint32_t sa = as0 + st * HG_STAGE_BYTES + (r * HG_LDS + ldc) * 2;
            asm volatile("cp.async.cg.shared.global [%0], [%1], 16;\n" :: "r"(sa), "l"(ga));
            const __half* gb = Bb + (size_t)r * K + kt * HG_BK + ldc;
            uint32_t sb = bs0 + st * HG_STAGE_BYTES + (r * HG_LDS + ldc) * 2;
            asm volatile("cp.async.cg.shared.global [%0], [%1], 16;\n" :: "r"(sb), "l"(gb));
        }
    };

    const int KT = K / HG_BK;
    load_tile(0, 0);
    asm volatile("cp.async.commit_group;\n");
    load_tile(1, 1);
    asm volatile("cp.async.commit_group;\n");

    float acc[4][4][4];
#pragma unroll
    for (int i = 0; i < 4; i++)
#pragma unroll
        for (int j = 0; j < 4; j++)
#pragma unroll
            for (int r = 0; r < 4; r++) acc[i][j][r] = 0.f;

    const int g  = lane >> 3;
    const int lr = lane & 7;
    const int a_row = ((g & 1) << 3) + lr;
    const int a_k   = (g >> 1) << 3;
    const int b_row = ((g >> 1) << 3) + lr;
    const int b_k   = (g & 1) << 3;

    for (int kt = 0; kt < KT; kt++) {
        asm volatile("cp.async.wait_group 1;\n");
        __syncthreads();
        if (kt + 2 < KT) load_tile(kt + 2, (kt + 2) % 3);
        asm volatile("cp.async.commit_group;\n");

        const int st = kt % 3;
        const uint32_t asb = as0 + st * HG_STAGE_BYTES;
        const uint32_t bsb = bs0 + st * HG_STAGE_BYTES;

#pragma unroll
        for (int ks = 0; ks < 2; ks++) {
            uint32_t af[4][4];
            uint32_t bf_[4][2];
#pragma unroll
            for (int mf = 0; mf < 4; mf++) {
                int row = wm * 64 + mf * 16 + a_row;
                ldsm4(af[mf], asb + (row * HG_LDS + ks * 16 + a_k) * 2);
            }
#pragma unroll
            for (int np = 0; np < 2; np++) {
                int row = wn * 32 + np * 16 + b_row;
                uint32_t tmp[4];
                ldsm4(tmp, bsb + (row * HG_LDS + ks * 16 + b_k) * 2);
                bf_[np*2][0] = tmp[0]; bf_[np*2][1] = tmp[1];
                bf_[np*2+1][0] = tmp[2]; bf_[np*2+1][1] = tmp[3];
            }
#pragma unroll
            for (int mf = 0; mf < 4; mf++)
#pragma unroll
                for (int nf = 0; nf < 4; nf++)
                    mma_f16(acc[mf][nf], af[mf], bf_[nf][0], bf_[nf][1]);
        }
    }

#pragma unroll
    for (int mf = 0; mf < 4; mf++) {
        int row = blockIdx.y * 128 + wm * 64 + mf * 16 + (lane >> 2);
#pragma unroll
        for (int nf = 0; nf < 4; nf++) {
            int col = blockIdx.x * 128 + wn * 32 + nf * 8 + (lane & 3) * 2;
            float2 v0 = {acc[mf][nf][0], acc[mf][nf][1]};
            float2 v1 = {acc[mf][nf][2], acc[mf][nf][3]};
            *(float2*)&C[(size_t)row * HID_ + col]       = v0;
            *(float2*)&C[(size_t)(row + 8) * HID_ + col] = v1;
        }
    }
}

// ---------------------------------------------------------------------------
// Launch
// ---------------------------------------------------------------------------
extern "C" void kernel_launch(void* const* d_in, const int* in_sizes, int n_in,
                              void* d_out, int out_size) {
    const float* hidden = (const float*)d_in[0];
    const int*   pos    = (const int*)  d_in[2];
    const float* wq     = (const float*)d_in[3];
    const float* wk     = (const float*)d_in[4];
    const float* wv     = (const float*)d_in[5];
    const float* wo     = (const float*)d_in[6];
    float* out = (float*)d_out;

    float *qb, *kb, *vb;
    __half *a2, *w3, *wo2, *o2, *qhp, *khp, *vthp;
    cudaGetSymbolAddress((void**)&qb, g_q);
    cudaGetSymbolAddress((void**)&kb, g_k);
    cudaGetSymbolAddress((void**)&vb, g_v);
    cudaGetSymbolAddress((void**)&a2, g_A2);
    cudaGetSymbolAddress((void**)&w3, g_W3);
    cudaGetSymbolAddress((void**)&wo2, g_Wo2);
    cudaGetSymbolAddress((void**)&o2, g_O2);
    cudaGetSymbolAddress((void**)&qhp, g_qh);
    cudaGetSymbolAddress((void**)&khp, g_kh);
    cudaGetSymbolAddress((void**)&vthp, g_vth);

    const int big4   = (M_TOT * HID_) / 4;
    const int small4 = (NKVD * HID_) / 4;
    cvtH_kernel<<<(big4 + 255) / 256, 256>>>(hidden, a2, big4);
    cvtH_kernel<<<(big4 + 255) / 256, 256>>>(wq, w3, big4);
    cvtH_kernel<<<(small4 + 255) / 256, 256>>>(wk, w3 + (size_t)HID_ * HID_, small4);
    cvtH_kernel<<<(small4 + 255) / 256, 256>>>(wv, w3 + (size_t)(HID_ + NKVD) * HID_, small4);
    cvtH_kernel<<<(big4 + 255) / 256, 256>>>(wo, wo2, big4);

    // fused QKV projection -> fp32 q/k/v (R13-proven epilogue)
    hgemm_nt<<<dim3(NQKV / 128, M_TOT / 128), 256>>>(a2, w3, qb, kb, vb, M_TOT, HID_);

    // fused rope + fp16 convert (Q prescaled by 1/sqrt(HD)*log2(e))
    const float QSC = 0.08838834764831845f * 1.4426950408889634f;
    ropecvt_kernel<<<(ROPE_TOTAL + 255) / 256, 256>>>(qb, kb, pos, qhp, khp, QSC);
    vt_kernel<<<(B_ * NKV_ * (HD_ / 4) * S_ + 255) / 256, 256>>>(vb, vthp);

    cudaFuncSetAttribute(flash_tc, cudaFuncAttributeMaxDynamicSharedMemorySize,
                         FLASH_SMEM_BYTES);
    flash_tc<<<dim3(S_ / 128, NH_, B_), 256, FLASH_SMEM_BYTES>>>(qhp, khp, vthp, o2);

    // output projection directly from fp16 O2
    hgemm_out<<<dim3(HID_ / 128, M_TOT / 128), 256>>>(o2, wo2, out, M_TOT, HID_);
}

// round 17
// speedup vs baseline: 1.3234x; 1.0049x over previous
#include <cuda_runtime.h>
#include <cuda_bf16.h>
#include <cuda_fp16.h>
#include <math.h>
#include <stdint.h>

// Problem constants
#define B_  2
#define S_  2048
#define HID_ 4096
#define NH_ 32
#define NKV_ 8
#define HD_ 128
#define M_TOT (B_ * S_)          // 4096
#define NKVD (NKV_ * HD_)        // 1024
#define NQKV (HID_ + 2 * NKVD)   // 6144 fused QKV output cols

// fp32 scratch (QKV projection outputs)
__device__ float g_q[(size_t)M_TOT * NH_ * HD_];
__device__ float g_k[(size_t)M_TOT * NKVD];
__device__ float g_v[(size_t)M_TOT * NKVD];

// fp16 scratch
__device__ __half g_A2 [(size_t)M_TOT * HID_];
__device__ __half g_W3 [(size_t)NQKV  * HID_];
__device__ __half g_Wo2[(size_t)HID_  * HID_];
__device__ __half g_O2 [(size_t)M_TOT * HID_];
__device__ __half g_qh [(size_t)M_TOT * NH_  * HD_];
__device__ __half g_kh [(size_t)M_TOT * NKVD];
__device__ __half g_vth[(size_t)M_TOT * NKVD];   // [b][kvh][d][s]

// ---------------------------------------------------------------------------
struct alignas(8) HF4 { __half v[4]; };

// prep: fused fp32->fp16 conversion for hidden + wq + wk + wv + wo
#define BIG4   ((M_TOT * HID_) / 4)      // 4.19M float4s
#define SMALL4 ((NKVD * HID_) / 4)       // 1.05M
#define PREP_TOTAL (3 * BIG4 + 2 * SMALL4)

__global__ void prep_kernel(const float* __restrict__ hidden,
                            const float* __restrict__ wq,
                            const float* __restrict__ wk,
                            const float* __restrict__ wv,
                            const float* __restrict__ wo,
                            __half* __restrict__ a2,
                            __half* __restrict__ w3,
                            __half* __restrict__ wo2) {
    int i = blockIdx.x * blockDim.x + threadIdx.x;
    if (i >= PREP_TOTAL) return;
    const float* src;
    __half* dst;
    int j = i;
    if (j < BIG4)                 { src = hidden; dst = a2; }
    else if ((j -= BIG4) < BIG4)  { src = wq;     dst = w3; }
    else if ((j -= BIG4) < SMALL4){ src = wk;     dst = w3 + (size_t)HID_ * HID_; }
    else if ((j -= SMALL4) < SMALL4){ src = wv;   dst = w3 + (size_t)(HID_ + NKVD) * HID_; }
    else                          { j -= SMALL4;  src = wo; dst = wo2; }

    float4 x = *(const float4*)(src + (size_t)j * 4);
    HF4 H;
    H.v[0] = __float2half_rn(x.x);
    H.v[1] = __float2half_rn(x.y);
    H.v[2] = __float2half_rn(x.z);
    H.v[3] = __float2half_rn(x.w);
    *(HF4*)(dst + (size_t)j * 4) = H;
}

// ropevt: fused RoPE(q,k fp32->fp16, q prescaled) + V transpose/convert
#define ROPE_TOTAL (B_ * S_ * (NH_ + NKV_) * 64)
#define VT_TOTAL   (B_ * NKV_ * (HD_ / 4) * S_)
#define RV_TOTAL   (ROPE_TOTAL + VT_TOTAL)

__global__ void ropevt_kernel(const float* __restrict__ q,
                              const float* __restrict__ k,
                              const float* __restrict__ v,
                              const int* __restrict__ pos_ids,
                              __half* __restrict__ qh,
                              __half* __restrict__ kh,
                              __half* __restrict__ th, float qsc) {
    int idx = blockIdx.x * blockDim.x + threadIdx.x;
    if (idx >= RV_TOTAL) return;
    if (idx < ROPE_TOTAL) {
        int d    = idx & 63;
        int rest = idx >> 6;
        int head = rest % (NH_ + NKV_);
        rest    /= (NH_ + NKV_);
        int s = rest % S_;
        int b = rest / S_;

        float inv = powf(10000.0f, -(float)d * (1.0f / 64.0f));
        float ang = (float)pos_ids[s] * inv;
        float c = cosf(ang), sn = sinf(ang);

        if (head < NH_) {
            size_t o = ((size_t)(b * S_ + s) * NH_ + head) * HD_;
            float x1 = q[o + d], x2 = q[o + d + 64];
            qh[o + d]      = __float2half_rn((x1 * c - x2 * sn) * qsc);
            qh[o + d + 64] = __float2half_rn((x2 * c + x1 * sn) * qsc);
        } else {
            size_t o = ((size_t)(b * S_ + s) * NKV_ + (head - NH_)) * HD_;
            float x1 = k[o + d], x2 = k[o + d + 64];
            kh[o + d]      = __float2half_rn(x1 * c - x2 * sn);
            kh[o + d + 64] = __float2half_rn(x2 * c + x1 * sn);
        }
    } else {
        int i = idx - ROPE_TOTAL;
        int s    = i % S_;
        int rest = i / S_;
        int d4   = rest % (HD_ / 4);
        rest    /= (HD_ / 4);
        int kvh  = rest % NKV_;
        int b    = rest / NKV_;
        float4 x = *(const float4*)(v + ((size_t)(b * S_ + s) * NKV_ + kvh) * HD_ + d4 * 4);
        float xs[4] = {x.x, x.y, x.z, x.w};
#pragma unroll
        for (int j = 0; j < 4; j++) {
            size_t o = ((size_t)(b * NKV_ + kvh) * HD_ + d4 * 4 + j) * S_ + s;
            th[o] = __float2half_rn(xs[j]);
        }
    }
}

// ---------------------------------------------------------------------------
// mma / ldmatrix helpers
// ---------------------------------------------------------------------------
__device__ __forceinline__ void ldsm4(uint32_t* r, uint32_t addr) {
    asm volatile("ldmatrix.sync.aligned.m8n8.x4.shared.b16 {%0,%1,%2,%3}, [%4];\n"
                 : "=r"(r[0]), "=r"(r[1]), "=r"(r[2]), "=r"(r[3]) : "r"(addr));
}
__device__ __forceinline__ void mma_f16(float* c, const uint32_t* a,
                                        uint32_t b0, uint32_t b1) {
    asm volatile("mma.sync.aligned.m16n8k16.row.col.f32.f16.f16.f32 "
                 "{%0,%1,%2,%3}, {%4,%5,%6,%7}, {%8,%9}, {%0,%1,%2,%3};\n"
                 : "+f"(c[0]), "+f"(c[1]), "+f"(c[2]), "+f"(c[3])
                 : "r"(a[0]), "r"(a[1]), "r"(a[2]), "r"(a[3]), "r"(b0), "r"(b1));
}
__device__ __forceinline__ uint32_t cvt_f16x2(float lo, float hi) {
    uint32_t r;
    asm("cvt.rn.f16x2.f32 %0, %1, %2;" : "=r"(r) : "f"(hi), "f"(lo));
    return r;
}

// ---------------------------------------------------------------------------
// fp16 tensor-core GEMM (NT): 128x128x32 tile, 256 threads, warp tile 64x32,
// 3-stage cp.async, 2 CTAs/SM. Epilogue routes QKV; fp32 output.
// ---------------------------------------------------------------------------
#define HG_BK 32
#define HG_LDS 40
#define HG_STAGE_ELEMS (128 * HG_LDS)
#define HG_STAGE_BYTES (HG_STAGE_ELEMS * 2)

__global__ __launch_bounds__(256, 2) void hgemm_nt(
    const __half* __restrict__ A, const __half* __restrict__ B,
    float* __restrict__ C0, float* __restrict__ C1, float* __restrict__ C2,
    int M, int K) {
    __shared__ __half As[3][HG_STAGE_ELEMS];
    __shared__ __half Bs[3][HG_STAGE_ELEMS];

    const int t    = threadIdx.x;
    const int lane = t & 31;
    const int w    = t >> 5;
    const int wm   = w >> 2;
    const int wn   = w & 3;

    const __half* Ab = A + (size_t)blockIdx.y * 128 * K;
    const __half* Bb = B + (size_t)blockIdx.x * 128 * K;

    const uint32_t as0 = (uint32_t)__cvta_generic_to_shared(&As[0][0]);
    const uint32_t bs0 = (uint32_t)__cvta_generic_to_shared(&Bs[0][0]);

    const int ldr = t >> 2;
    const int ldc = (t & 3) * 8;

    auto load_tile = [&](int kt, int st) {
#pragma unroll
        for (int it = 0; it < 2; it++) {
            int r = ldr + it * 64;
            const __half* ga = Ab + (size_t)r * K + kt * HG_BK + ldc;
            uint32_t sa = as0 + st * HG_STAGE_BYTES + (r * HG_LDS + ldc) * 2;
            asm volatile("cp.async.cg.shared.global [%0], [%1], 16;\n" :: "r"(sa), "l"(ga));
            const __half* gb = Bb + (size_t)r * K + kt * HG_BK + ldc;
            uint32_t sb = bs0 + st * HG_STAGE_BYTES + (r * HG_LDS + ldc) * 2;
            asm volatile("cp.async.cg.shared.global [%0], [%1], 16;\n" :: "r"(sb), "l"(gb));
        }
    };

    const int KT = K / HG_BK;
    load_tile(0, 0);
    asm volatile("cp.async.commit_group;\n");
    load_tile(1, 1);
    asm volatile("cp.async.commit_group;\n");

    float acc[4][4][4];
#pragma unroll
    for (int i = 0; i < 4; i++)
#pragma unroll
        for (int j = 0; j < 4; j++)
#pragma unroll
            for (int r = 0; r < 4; r++) acc[i][j][r] = 0.f;

    const int g  = lane >> 3;
    const int lr = lane & 7;
    const int a_row = ((g & 1) << 3) + lr;
    const int a_k   = (g >> 1) << 3;
    const int b_row = ((g >> 1) << 3) + lr;
    const int b_k   = (g & 1) << 3;

    for (int kt = 0; kt < KT; kt++) {
        asm volatile("cp.async.wait_group 1;\n");
        __syncthreads();
        if (kt + 2 < KT) load_tile(kt + 2, (kt + 2) % 3);
        asm volatile("cp.async.commit_group;\n");

        const int st = kt % 3;
        const uint32_t asb = as0 + st * HG_STAGE_BYTES;
        const uint32_t bsb = bs0 + st * HG_STAGE_BYTES;

#pragma unroll
        for (int ks = 0; ks < 2; ks++) {
            uint32_t af[4][4];
            uint32_t bf_[4][2];
#pragma unroll
            for (int mf = 0; mf < 4; mf++) {
                int row = wm * 64 + mf * 16 + a_row;
                ldsm4(af[mf], asb + (row * HG_LDS + ks * 16 + a_k) * 2);
            }
#pragma unroll
            for (int np = 0; np < 2; np++) {
                int row = wn * 32 + np * 16 + b_row;
                uint32_t tmp[4];
                ldsm4(tmp, bsb + (row * HG_LDS + ks * 16 + b_k) * 2);
                bf_[np*2][0] = tmp[0]; bf_[np*2][1] = tmp[1];
                bf_[np*2+1][0] = tmp[2]; bf_[np*2+1][1] = tmp[3];
            }
#pragma unroll
            for (int mf = 0; mf < 4; mf++)
#pragma unroll
                for (int nf = 0; nf < 4; nf++)
                    mma_f16(acc[mf][nf], af[mf], bf_[nf][0], bf_[nf][1]);
        }
    }

    const int gc0 = blockIdx.x * 128;
    float* Cd; int cstride, cbase;
    if (gc0 < HID_)                { Cd = C0; cstride = NH_ * HD_; cbase = 0; }
    else if (gc0 < HID_ + NKVD)    { Cd = C1; cstride = NKVD;      cbase = HID_; }
    else                           { Cd = C2; cstride = NKVD;      cbase = HID_ + NKVD; }

#pragma unroll
    for (int mf = 0; mf < 4; mf++) {
        int row = blockIdx.y * 128 + wm * 64 + mf * 16 + (lane >> 2);
#pragma unroll
        for (int nf = 0; nf < 4; nf++) {
            int col = gc0 + wn * 32 + nf * 8 + (lane & 3) * 2 - cbase;
            float2 v0 = {acc[mf][nf][0], acc[mf][nf][1]};
            float2 v1 = {acc[mf][nf][2], acc[mf][nf][3]};
            *(float2*)&Cd[(size_t)row * cstride + col]       = v0;
            *(float2*)&Cd[(size_t)(row + 8) * cstride + col] = v1;
        }
    }
}

// ---------------------------------------------------------------------------
// Tensor-core flash attention, single-term fp16, fp16 output.
// ---------------------------------------------------------------------------
#define FQ_LDS 136
#define FV_LDS 72
#define F_Q 0
#define F_STAGE0 17408
#define F_STAGE (8704 + 9216)
#define F_K 0
#define F_VT 8704
#define FLASH_SMEM_ELEMS (F_STAGE0 + 2 * F_STAGE)
#define FLASH_SMEM_BYTES (FLASH_SMEM_ELEMS * 2)

__global__ __launch_bounds__(256, 1) void flash_tc(
    const __half* __restrict__ qh, const __half* __restrict__ kh,
    const __half* __restrict__ vth, __half* __restrict__ o) {
    const int qt  = gridDim.x - 1 - blockIdx.x;
    const int h   = blockIdx.y;
    const int b   = blockIdx.z;
    const int kvh = h >> 2;

    extern __shared__ __half fsm[];
    const uint32_t sb = (uint32_t)__cvta_generic_to_shared(fsm);

    const int t    = threadIdx.x;
    const int lane = t & 31;
    const int w    = t >> 5;

    {
        int r = t >> 1;
        const __half* gq = qh + ((size_t)(b * S_ + qt * 128 + r) * NH_ + h) * HD_;
#pragma unroll
        for (int j = 0; j < 8; j++) {
            int col = (t & 1) * 64 + j * 8;
            uint32_t sh = sb + (F_Q + r * FQ_LDS + col) * 2;
            asm volatile("cp.async.cg.shared.global [%0], [%1], 16;\n" :: "r"(sh), "l"(gq + col));
        }
        asm volatile("cp.async.commit_group;\n");
    }

    auto load_kv = [&](int kt, int st) {
        uint32_t stb = sb + (F_STAGE0 + st * F_STAGE) * 2;
        {
            int r  = t >> 2;
            int cb = (t & 3) * 32;
            size_t go = ((size_t)(b * S_ + kt * 64 + r) * NKV_ + kvh) * HD_;
#pragma unroll
            for (int j = 0; j < 4; j++) {
                int col = cb + j * 8;
                asm volatile("cp.async.cg.shared.global [%0], [%1], 16;\n"
                             :: "r"(stb + (F_K + r * FQ_LDS + col) * 2), "l"(kh + go + col));
            }
        }
        {
            int rv = t >> 1;
            int cv = (t & 1) * 32;
            size_t go = ((size_t)(b * NKV_ + kvh) * HD_ + rv) * S_ + kt * 64;
#pragma unroll
            for (int j = 0; j < 4; j++) {
                int col = cv + j * 8;
                asm volatile("cp.async.cg.shared.global [%0], [%1], 16;\n"
                             :: "r"(stb + (F_VT + rv * FV_LDS + col) * 2), "l"(vth + go + col));
            }
        }
    };

    const int ktmax = 2 * qt + 1;
    load_kv(0, 0);
    asm volatile("cp.async.commit_group;\n");
    if (ktmax >= 1) load_kv(1, 1);
    asm volatile("cp.async.commit_group;\n");

    const int g  = lane >> 3;
    const int lr = lane & 7;
    const int a_row = ((g & 1) << 3) + lr;
    const int a_k   = (g >> 1) << 3;
    const int b_row = ((g >> 1) << 3) + lr;
    const int b_k   = (g & 1) << 3;

    float out[16][4];
#pragma unroll
    for (int i = 0; i < 16; i++)
#pragma unroll
        for (int j = 0; j < 4; j++) out[i][j] = 0.f;
    float m0 = -INFINITY, m1 = -INFINITY, l0 = 0.f, l1 = 0.f;

    const int qrow_base = qt * 128 + w * 16;

    for (int kt = 0; kt <= ktmax; kt++) {
        asm volatile("cp.async.wait_group 1;\n");
        __syncthreads();
        const int st = kt & 1;
        const uint32_t stb = sb + (F_STAGE0 + st * F_STAGE) * 2;

        if (kt * 64 <= qrow_base + 15) {
            float accs[8][4];
#pragma unroll
            for (int i = 0; i < 8; i++)
#pragma unroll
                for (int j = 0; j < 4; j++) accs[i][j] = 0.f;

#pragma unroll
            for (int kc = 0; kc < 8; kc++) {
                uint32_t aH[4];
                ldsm4(aH, sb + (F_Q + (w * 16 + a_row) * FQ_LDS + kc * 16 + a_k) * 2);
#pragma unroll
                for (int nf2 = 0; nf2 < 4; nf2++) {
                    uint32_t bh[4];
                    ldsm4(bh, stb + (F_K + (nf2 * 16 + b_row) * FQ_LDS + kc * 16 + b_k) * 2);
                    mma_f16(accs[nf2 * 2],     aH, bh[0], bh[1]);
                    mma_f16(accs[nf2 * 2 + 1], aH, bh[2], bh[3]);
                }
            }

            if (kt * 64 + 63 > qrow_base) {
                int r0 = qrow_base + (lane >> 2);
#pragma unroll
                for (int nf = 0; nf < 8; nf++) {
#pragma unroll
                    for (int e = 0; e < 4; e++) {
                        int col = kt * 64 + nf * 8 + (lane & 3) * 2 + (e & 1);
                        int row = r0 + (e >> 1) * 8;
                        if (col > row) accs[nf][e] = -1.0e30f;
                    }
                }
            }

            float mx0 = -INFINITY, mx1 = -INFINITY;
#pragma unroll
            for (int nf = 0; nf < 8; nf++) {
                mx0 = fmaxf(mx0, fmaxf(accs[nf][0], accs[nf][1]));
                mx1 = fmaxf(mx1, fmaxf(accs[nf][2], accs[nf][3]));
            }
            mx0 = fmaxf(mx0, __shfl_xor_sync(0xffffffffu, mx0, 1));
            mx0 = fmaxf(mx0, __shfl_xor_sync(0xffffffffu, mx0, 2));
            mx1 = fmaxf(mx1, __shfl_xor_sync(0xffffffffu, mx1, 1));
            mx1 = fmaxf(mx1, __shfl_xor_sync(0xffffffffu, mx1, 2));
            float mn0 = fmaxf(m0, mx0), mn1 = fmaxf(m1, mx1);
            float c0 = exp2f(m0 - mn0), c1 = exp2f(m1 - mn1);
            m0 = mn0; m1 = mn1;

            float s0 = 0.f, s1 = 0.f;
#pragma unroll
            for (int nf = 0; nf < 8; nf++) {
                accs[nf][0] = exp2f(accs[nf][0] - mn0);
                accs[nf][1] = exp2f(accs[nf][1] - mn0);
                accs[nf][2] = exp2f(accs[nf][2] - mn1);
                accs[nf][3] = exp2f(accs[nf][3] - mn1);
                s0 += accs[nf][0] + accs[nf][1];
                s1 += accs[nf][2] + accs[nf][3];
            }
            s0 += __shfl_xor_sync(0xffffffffu, s0, 1);
            s0 += __shfl_xor_sync(0xffffffffu, s0, 2);
            s1 += __shfl_xor_sync(0xffffffffu, s1, 1);
            s1 += __shfl_xor_sync(0xffffffffu, s1, 2);
            l0 = l0 * c0 + s0;
            l1 = l1 * c1 + s1;

            uint32_t pH[4][4];
#pragma unroll
            for (int kc2 = 0; kc2 < 4; kc2++) {
#pragma unroll
                for (int q4 = 0; q4 < 4; q4++) {
                    int nf = kc2 * 2 + (q4 >> 1);
                    int e0 = (q4 & 1) * 2;
                    pH[kc2][q4] = cvt_f16x2(accs[nf][e0], accs[nf][e0 + 1]);
                }
            }

#pragma unroll
            for (int i = 0; i < 16; i++) {
                out[i][0] *= c0; out[i][1] *= c0;
                out[i][2] *= c1; out[i][3] *= c1;
            }

#pragma unroll
            for (int kc2 = 0; kc2 < 4; kc2++) {
#pragma unroll
                for (int nd = 0; nd < 8; nd++) {
                    uint32_t bh[4];
                    ldsm4(bh, stb + (F_VT + (nd * 16 + b_row) * FV_LDS + kc2 * 16 + b_k) * 2);
                    mma_f16(out[nd * 2],     pH[kc2], bh[0], bh[1]);
                    mma_f16(out[nd * 2 + 1], pH[kc2], bh[2], bh[3]);
                }
            }
        }

        __syncthreads();
        if (kt + 2 <= ktmax) load_kv(kt + 2, st);
        asm volatile("cp.async.commit_group;\n");
    }

    float inv0 = 1.0f / l0, inv1 = 1.0f / l1;
    int r0 = qt * 128 + w * 16 + (lane >> 2);
#pragma unroll
    for (int nfd = 0; nfd < 16; nfd++) {
        int col = nfd * 8 + (lane & 3) * 2;
        __half2 v0 = __floats2half2_rn(out[nfd][0] * inv0, out[nfd][1] * inv0);
        __half2 v1 = __floats2half2_rn(out[nfd][2] * inv1, out[nfd][3] * inv1);
        *(__half2*)&o[((size_t)(b * S_ + r0) * NH_ + h) * HD_ + col]       = v0;
        *(__half2*)&o[((size_t)(b * S_ + r0 + 8) * NH_ + h) * HD_ + col]   = v1;
    }
}

// ---------------------------------------------------------------------------
// Output-projection GEMM: fp16 in, fp32 out (plain)
// ---------------------------------------------------------------------------
__global__ __launch_bounds__(256, 2) void hgemm_out(
    const __half* __restrict__ A, const __half* __restrict__ B,
    float* __restrict__ C, int M, int K) {
    __shared__ __half As[3][HG_STAGE_ELEMS];
    __shared__ __half Bs[3][HG_STAGE_ELEMS];

    const int t    = threadIdx.x;
    const int lane = t & 31;
    const int w    = t >> 5;
    const int wm   = w >> 2;
    const int wn   = w & 3;

    const __half* Ab = A + (size_t)blockIdx.y * 128 * K;
    const __half* Bb = B + (size_t)blockIdx.x * 128 * K;

    const uint32_t as0 = (uint32_t)__cvta_generic_to_shared(&As[0][0]);
    const uint32_t bs0 = (uint32_t)__cvta_generic_to_shared(&Bs[0][0]);

    const int ldr = t >> 2;
    const int ldc = (t & 3) * 8;

    auto load_tile = [&](int kt, int st) {
#pragma unroll
        for (int it = 0; it < 2; it++) {
            int r = ldr + it * 64;
            const __half* ga = Ab + (size_t)r * K + kt * HG_BK + ldc;
            uint32_t sa = as0 + st * HG_STAGE_BYTES + (r * HG_LDS + ldc) * 2;
            asm volatile("cp.async.cg.shared.global [%0], [%1], 16;\n" :: "r"(sa), "l"(ga));
            const __half* gb = Bb + (size_t)r * K + kt * HG_BK + ldc;
            uint32_t sb = bs0 + st * HG_STAGE_BYTES + (r * HG_LDS + ldc) * 2;
            asm volatile("cp.async.cg.shared.global [%0], [%1], 16;\n" :: "r"(sb), "l"(gb));
        }
    };

    const int KT = K / HG_BK;
    load_tile(0, 0);
    asm volatile("cp.async.commit_group;\n");
    load_tile(1, 1);
    asm volatile("cp.async.commit_group;\n");

    float acc[4][4][4];
#pragma unroll
    for (int i = 0; i < 4; i++)
#pragma unroll
        for (int j = 0; j < 4; j++)
#pragma unroll
            for (int r = 0; r < 4; r++) acc[i][j][r] = 0.f;

    const int g  = lane >> 3;
    const int lr = lane & 7;
    const int a_row = ((g & 1) << 3) + lr;
    const int a_k   = (g >> 1) << 3;
    const int b_row = ((g >> 1) << 3) + lr;
    const int b_k   = (g & 1) << 3;

    for (int kt = 0; kt < KT; kt++) {
        asm volatile("cp.async.wait_group 1;\n");
        __syncthreads();
        if (kt + 2 < KT) load_tile(kt + 2, (kt + 2) % 3);
        asm volatile("cp.async.commit_group;\n");

        const int st = kt % 3;
        const uint32_t asb = as0 + st * HG_STAGE_BYTES;
        const uint32_t bsb = bs0 + st * HG_STAGE_BYTES;

#pragma unroll
        for (int ks = 0; ks < 2; ks++) {
            uint32_t af[4][4];
            uint32_t bf_[4][2];
#pragma unroll
            for (int mf = 0; mf < 4; mf++) {
                int row = wm * 64 + mf * 16 + a_row;
                ldsm4(af[mf], asb + (row * HG_LDS + ks * 16 + a_k) * 2);
            }
#pragma unroll
            for (int np = 0; np < 2; np++) {
                int row = wn * 32 + np * 16 + b_row;
                uint32_t tmp[4];
                ldsm4(tmp, bsb + (row * HG_LDS + ks * 16 + b_k) * 2);
                bf_[np*2][0] = tmp[0]; bf_[np*2][1] = tmp[1];
                bf_[np*2+1][0] = tmp[2]; bf_[np*2+1][1] = tmp[3];
            }
#pragma unroll
            for (int mf = 0; mf < 4; mf++)
#pragma unroll
                for (int nf = 0; nf < 4; nf++)
                    mma_f16(acc[mf][nf], af[mf], bf_[nf][0], bf_[nf][1]);
        }
    }

#pragma unroll
    for (int mf = 0; mf < 4; mf++) {
        int row = blockIdx.y * 128 + wm * 64 + mf * 16 + (lane >> 2);
#pragma unroll
        for (int nf = 0; nf < 4; nf++) {
            int col = blockIdx.x * 128 + wn * 32 + nf * 8 + (lane & 3) * 2;
            float2 v0 = {acc[mf][nf][0], acc[mf][nf][1]};
            float2 v1 = {acc[mf][nf][2], acc[mf][nf][3]};
            *(float2*)&C[(size_t)row * HID_ + col]       = v0;
            *(float2*)&C[(size_t)(row + 8) * HID_ + col] = v1;
        }
    }
}

// ---------------------------------------------------------------------------
// Launch
// ---------------------------------------------------------------------------
extern "C" void kernel_launch(void* const* d_in, const int* in_sizes, int n_in,
                              void* d_out, int out_size) {
    const float* hidden = (const float*)d_in[0];
    const int*   pos    = (const int*)  d_in[2];
    const float* wq     = (const float*)d_in[3];
    const float* wk     = (const float*)d_in[4];
    const float* wv     = (const float*)d_in[5];
    const float* wo     = (const float*)d_in[6];
    float* out = (float*)d_out;

    float *qb, *kb, *vb;
    __half *a2, *w3, *wo2, *o2, *qhp, *khp, *vthp;
    cudaGetSymbolAddress((void**)&qb, g_q);
    cudaGetSymbolAddress((void**)&kb, g_k);
    cudaGetSymbolAddress((void**)&vb, g_v);
    cudaGetSymbolAddress((void**)&a2, g_A2);
    cudaGetSymbolAddress((void**)&w3, g_W3);
    cudaGetSymbolAddress((void**)&wo2, g_Wo2);
    cudaGetSymbolAddress((void**)&o2, g_O2);
    cudaGetSymbolAddress((void**)&qhp, g_qh);
    cudaGetSymbolAddress((void**)&khp, g_kh);
    cudaGetSymbolAddress((void**)&vthp, g_vth);

    // fused fp32->fp16 conversions (hidden + 4 weights) in ONE launch
    prep_kernel<<<(PREP_TOTAL + 255) / 256, 256>>>(
        hidden, wq, wk, wv, wo, a2, w3, wo2);

    // fused QKV projection -> fp32 q/k/v
    hgemm_nt<<<dim3(NQKV / 128, M_TOT / 128), 256>>>(a2, w3, qb, kb, vb, M_TOT, HID_);

    // fused rope-convert + V transpose in ONE launch
    const float QSC = 0.08838834764831845f * 1.4426950408889634f;
    ropevt_kernel<<<(RV_TOTAL + 255) / 256, 256>>>(qb, kb, vb, pos, qhp, khp, vthp, QSC);

    cudaFuncSetAttribute(flash_tc, cudaFuncAttributeMaxDynamicSharedMemorySize,
                         FLASH_SMEM_BYTES);
    flash_tc<<<dim3(S_ / 128, NH_, B_), 256, FLASH_SMEM_BYTES>>>(qhp, khp, vthp, o2);

    // output projection directly from fp16 O2
    hgemm_out<<<dim3(HID_ / 128, M_TOT / 128), 256>>>(o2, wo2, out, M_TOT, HID_);
}